// round 2
// baseline (speedup 1.0000x reference)
#include <cuda_runtime.h>
#include <math.h>

#define HH 256
#define WW 256
#define HW 65536
#define NB 8
#define NCC 3          // channels 1..3 kept
#define NSLICE 24      // NB*NCC
#define NPIX (NB*HW)   // 524288
#define NFIELD 4       // 0: mask_p, 1: ~mask_p, 2: mask_t, 3: ~mask_t
#define CAP 512        // INF = H + W in reference

// -------- device scratch (no allocations allowed) --------
__device__ uchar4         g_masks4[NPIX / 4];               // bits 0..2 mask_p cc, 3..5 mask_t cc
__device__ float4         g_p4[NSLICE * HW / 4];            // softmax probs, channels 1..3
__device__ unsigned short g_vert[NFIELD * NSLICE * HW];     // vertical 1D distances (<=512)
__device__ int            g_cnt[2 * NSLICE];                // [0..23] p-counts, [24..47] t-counts
__device__ double         g_acc;

// -------- kernel 0: zero accumulators --------
__global__ void k_init() {
    int t = threadIdx.x;
    if (t < 2 * NSLICE) g_cnt[t] = 0;
    if (t == 0) g_acc = 0.0;
}

// per-pixel softmax(4) + argmax(4) -> probs of ch 1..3 + 6 mask bits
__device__ __forceinline__ void pixel_work(float s0, float s1, float s2, float s3,
                                           float t0, float t1, float t2, float t3,
                                           float& p1, float& p2, float& p3,
                                           unsigned& mk) {
    float m  = fmaxf(fmaxf(s0, s1), fmaxf(s2, s3));
    float e0 = __expf(s0 - m), e1 = __expf(s1 - m), e2 = __expf(s2 - m), e3 = __expf(s3 - m);
    float inv = 1.0f / (e0 + e1 + e2 + e3);
    p1 = e1 * inv; p2 = e2 * inv; p3 = e3 * inv;

    int lab = 0; float best = t0;            // first-index-wins (matches jnp.argmax)
    if (t1 > best) { best = t1; lab = 1; }
    if (t2 > best) { best = t2; lab = 2; }
    if (t3 > best) { best = t3; lab = 3; }

    mk = 0;
    if (p1 > 0.5f) mk |= 1u;
    if (p2 > 0.5f) mk |= 2u;
    if (p3 > 0.5f) mk |= 4u;
    if (lab == 1)  mk |= 8u;
    if (lab == 2)  mk |= 16u;
    if (lab == 3)  mk |= 32u;
}

// -------- kernel 1: softmax + argmax + masks + per-slice counts (4 px/thread) --------
__global__ void __launch_bounds__(256) k_prep(const float4* __restrict__ S4,
                                              const float4* __restrict__ T4) {
    int q  = blockIdx.x * 256 + threadIdx.x;   // quad index, 0 .. NPIX/4-1
    int b  = q >> 14;                          // 16384 quads per image; blocks never straddle b
    int pq = q & 16383;

    const float4* s = S4 + (size_t)b * 4 * 16384 + pq;
    float4 s0 = s[0], s1 = s[16384], s2 = s[2 * 16384], s3 = s[3 * 16384];
    const float4* t = T4 + (size_t)b * 4 * 16384 + pq;
    float4 t0 = t[0], t1 = t[16384], t2 = t[2 * 16384], t3 = t[3 * 16384];

    float4 P1, P2, P3;
    unsigned m0, m1, m2, m3;
    pixel_work(s0.x, s1.x, s2.x, s3.x, t0.x, t1.x, t2.x, t3.x, P1.x, P2.x, P3.x, m0);
    pixel_work(s0.y, s1.y, s2.y, s3.y, t0.y, t1.y, t2.y, t3.y, P1.y, P2.y, P3.y, m1);
    pixel_work(s0.z, s1.z, s2.z, s3.z, t0.z, t1.z, t2.z, t3.z, P1.z, P2.z, P3.z, m2);
    pixel_work(s0.w, s1.w, s2.w, s3.w, t0.w, t1.w, t2.w, t3.w, P1.w, P2.w, P3.w, m3);

    g_masks4[q] = make_uchar4((unsigned char)m0, (unsigned char)m1,
                              (unsigned char)m2, (unsigned char)m3);
    int base = (b * 3) * 16384 + pq;
    g_p4[base]             = P1;
    g_p4[base + 16384]     = P2;
    g_p4[base + 2 * 16384] = P3;

    // per-slice popcounts (for valid = any() && !all())
    __shared__ int scnt[6];
    if (threadIdx.x < 6) scnt[threadIdx.x] = 0;
    __syncthreads();
    #pragma unroll
    for (int bit = 0; bit < 6; bit++) {
        int c = ((m0 >> bit) & 1) + ((m1 >> bit) & 1) + ((m2 >> bit) & 1) + ((m3 >> bit) & 1);
        int tot = __reduce_add_sync(0xffffffffu, c);
        if ((threadIdx.x & 31) == 0) atomicAdd(&scnt[bit], tot);
    }
    __syncthreads();
    if (threadIdx.x < 3)      atomicAdd(&g_cnt[b * 3 + threadIdx.x], scnt[threadIdx.x]);
    else if (threadIdx.x < 6) atomicAdd(&g_cnt[NSLICE + b * 3 + threadIdx.x - 3], scnt[threadIdx.x]);
}

// -------- kernel 2: vertical EDT via bit-packed nearest-zero search --------
// Each block: one (field, slice). Thread = column. Column's 256 mask bits live
// in smem as 8 u32 words; vertical distance per row found with ffs/clz.
__global__ void __launch_bounds__(256) k_vert() {
    int bs  = blockIdx.x;          // 0..95 = f*NSLICE + s
    int f   = bs / NSLICE;
    int s   = bs % NSLICE;
    int col = threadIdx.x;
    int b   = s / 3, cc = s % 3;
    int bit = (f >= 2 ? 3 : 0) + cc;
    unsigned inv = (f & 1) ? 0xFFFFFFFFu : 0u;   // odd fields use complement mask

    const unsigned char* mk = ((const unsigned char*)g_masks4) + (size_t)b * HW + col;
    unsigned short* gv = g_vert + ((size_t)f * NSLICE + s) * HW + col;

    __shared__ unsigned bits[8][WW];             // [word][col] — conflict-free
    #pragma unroll
    for (int w = 0; w < 8; w++) {
        unsigned acc = 0;
        #pragma unroll
        for (int i2 = 0; i2 < 32; i2++)
            acc |= (unsigned)((mk[(w * 32 + i2) * WW] >> bit) & 1) << i2;
        bits[w][col] = acc ^ inv;                // 1 = mask true, 0 = mask false (target)
    }
    // no __syncthreads needed: each thread reads only its own column's words

    for (int i = 0; i < HH; i++) {
        int w = i >> 5, off = i & 31;
        unsigned cw = ~bits[w][col];             // set bit = zero pixel

        // nearest zero at or below row i
        int ddn = CAP;
        unsigned x = cw & (0xFFFFFFFFu << off);
        if (x) ddn = (__ffs(x) - 1) - off;
        else {
            for (int w2 = w + 1; w2 < 8; w2++) {
                unsigned z = ~bits[w2][col];
                if (z) { ddn = w2 * 32 + (__ffs(z) - 1) - i; break; }
            }
        }
        // nearest zero at or above row i
        int dup = CAP;
        unsigned y = cw & (0xFFFFFFFFu >> (31 - off));
        if (y) dup = off - (31 - __clz(y));
        else {
            for (int w2 = w - 1; w2 >= 0; w2--) {
                unsigned z = ~bits[w2][col];
                if (z) { dup = i - (w2 * 32 + 31 - __clz(z)); break; }
            }
        }
        gv[i * WW] = (unsigned short)min(dup, ddn);   // 512 iff column all-true (matches cap)
    }
}

// exact outward search: min_k G[k] + (j-k)^2, early exit when d*d >= best
__device__ __forceinline__ int edt_search(const int* __restrict__ G, int j) {
    int best = G[j];
    #pragma unroll 4
    for (int d = 1; d < WW; d++) {
        int dd = d * d;
        if (dd >= best) break;
        int jm = j - d, jp = j + d;
        if (jm >= 0) best = min(best, G[jm] + dd);
        if (jp < WW) best = min(best, G[jp] + dd);
    }
    return best;
}

// -------- kernel 3: horizontal EDT (early exit) + fused loss reduction --------
__global__ void __launch_bounds__(256) k_row() {
    int s   = blockIdx.x >> 8;     // slice 0..23
    int row = blockIdx.x & 255;
    int j   = threadIdx.x;
    int b   = s / 3, cc = s % 3;

    __shared__ int G[4][WW];
    #pragma unroll
    for (int f = 0; f < 4; f++) {
        int g = g_vert[((size_t)f * NSLICE + s) * HW + row * WW + j];
        G[f][j] = g * g;
    }
    __syncthreads();

    int cp = g_cnt[s], ct = g_cnt[NSLICE + s];
    float vp = (cp > 0 && cp < HW) ? 1.0f : 0.0f;
    float vt = (ct > 0 && ct < HW) ? 1.0f : 0.0f;

    int dp = edt_search(G[0], j) + edt_search(G[1], j);
    int dt = edt_search(G[2], j) + edt_search(G[3], j);

    float p  = ((const float*)g_p4)[(size_t)s * HW + row * WW + j];
    unsigned mb = ((const unsigned char*)g_masks4)[(size_t)b * HW + row * WW + j];
    float tg = (float)((mb >> (3 + cc)) & 1u);
    float err = (p - tg) * (p - tg);
    float val = err * ((float)dp * vp + (float)dt * vt);

    // block reduction -> double atomic
    #pragma unroll
    for (int o = 16; o; o >>= 1) val += __shfl_down_sync(0xffffffffu, val, o);
    __shared__ float wsum[8];
    if ((threadIdx.x & 31) == 0) wsum[threadIdx.x >> 5] = val;
    __syncthreads();
    if (threadIdx.x == 0) {
        float ssum = 0.0f;
        #pragma unroll
        for (int w = 0; w < 8; w++) ssum += wsum[w];
        atomicAdd(&g_acc, (double)ssum);
    }
}

// -------- kernel 4: finalize --------
__global__ void k_final(float* out) {
    double mean = g_acc / (double)(NSLICE * HW);
    out[0] = (float)log(mean + 1.0);
}

extern "C" void kernel_launch(void* const* d_in, const int* in_sizes, int n_in,
                              void* d_out, int out_size) {
    const float4* S = (const float4*)d_in[0];   // preds_S (8,4,256,256)
    const float4* T = (const float4*)d_in[1];   // preds_T (8,4,256,256)
    (void)in_sizes; (void)n_in; (void)out_size; // target (d_in[2]) unused by reference

    k_init<<<1, 64>>>();
    k_prep<<<NPIX / 4 / 256, 256>>>(S, T);
    k_vert<<<NFIELD * NSLICE, 256>>>();
    k_row<<<NSLICE * HH, 256>>>();
    k_final<<<1, 1>>>((float*)d_out);
}

// round 3
// speedup vs baseline: 3.0328x; 3.0328x over previous
#include <cuda_runtime.h>
#include <math.h>

#define HH 256
#define WW 256
#define HW 65536
#define NB 8
#define NSLICE 24      // NB * 3 kept channels
#define NPIX (NB*HW)   // 524288
#define CAP 512        // INF = H + W in reference

// -------- device scratch (no allocations allowed) --------
__device__ uchar4   g_masks4[NPIX / 4];          // per-pixel: bits 0..2 mask_p cc, 3..5 mask_t cc
__device__ float4   g_p4[NSLICE * HW / 4];       // softmax probs, channels 1..3
__device__ unsigned g_bits[2 * NSLICE * 8 * WW]; // column-packed bits [plane][slice][word][col]
__device__ int      g_cnt[2 * NSLICE];           // [0..23] p-counts, [24..47] t-counts
__device__ double   g_acc;

// -------- kernel 0: zero accumulators --------
__global__ void k_init() {
    int t = threadIdx.x;
    if (t < 2 * NSLICE) g_cnt[t] = 0;
    if (t == 0) g_acc = 0.0;
}

// per-pixel softmax(4) + argmax(4) -> probs of ch 1..3 + 6 mask bits
__device__ __forceinline__ void pixel_work(float s0, float s1, float s2, float s3,
                                           float t0, float t1, float t2, float t3,
                                           float& p1, float& p2, float& p3,
                                           unsigned& mk) {
    float m  = fmaxf(fmaxf(s0, s1), fmaxf(s2, s3));
    float e0 = __expf(s0 - m), e1 = __expf(s1 - m), e2 = __expf(s2 - m), e3 = __expf(s3 - m);
    float inv = 1.0f / (e0 + e1 + e2 + e3);
    p1 = e1 * inv; p2 = e2 * inv; p3 = e3 * inv;

    int lab = 0; float best = t0;            // first-index-wins (matches jnp.argmax)
    if (t1 > best) { best = t1; lab = 1; }
    if (t2 > best) { best = t2; lab = 2; }
    if (t3 > best) { best = t3; lab = 3; }

    mk = 0;
    if (p1 > 0.5f) mk |= 1u;
    if (p2 > 0.5f) mk |= 2u;
    if (p3 > 0.5f) mk |= 4u;
    if (lab == 1)  mk |= 8u;
    if (lab == 2)  mk |= 16u;
    if (lab == 3)  mk |= 32u;
}

// -------- kernel 1: softmax + argmax + masks (4 px/thread, no reductions) --------
__global__ void __launch_bounds__(256) k_prep(const float4* __restrict__ S4,
                                              const float4* __restrict__ T4) {
    int q  = blockIdx.x * 256 + threadIdx.x;   // quad index
    int b  = q >> 14;                          // 16384 quads per image
    int pq = q & 16383;

    const float4* s = S4 + (size_t)b * 4 * 16384 + pq;
    float4 s0 = s[0], s1 = s[16384], s2 = s[2 * 16384], s3 = s[3 * 16384];
    const float4* t = T4 + (size_t)b * 4 * 16384 + pq;
    float4 t0 = t[0], t1 = t[16384], t2 = t[2 * 16384], t3 = t[3 * 16384];

    float4 P1, P2, P3;
    unsigned m0, m1, m2, m3;
    pixel_work(s0.x, s1.x, s2.x, s3.x, t0.x, t1.x, t2.x, t3.x, P1.x, P2.x, P3.x, m0);
    pixel_work(s0.y, s1.y, s2.y, s3.y, t0.y, t1.y, t2.y, t3.y, P1.y, P2.y, P3.y, m1);
    pixel_work(s0.z, s1.z, s2.z, s3.z, t0.z, t1.z, t2.z, t3.z, P1.z, P2.z, P3.z, m2);
    pixel_work(s0.w, s1.w, s2.w, s3.w, t0.w, t1.w, t2.w, t3.w, P1.w, P2.w, P3.w, m3);

    g_masks4[q] = make_uchar4((unsigned char)m0, (unsigned char)m1,
                              (unsigned char)m2, (unsigned char)m3);
    int base = (b * 3) * 16384 + pq;
    g_p4[base]             = P1;
    g_p4[base + 16384]     = P2;
    g_p4[base + 2 * 16384] = P3;
}

// -------- kernel 2: transpose masks into column-packed bit planes + counts --------
// grid = 8 images * 8 word-groups; thread = column.
__global__ void __launch_bounds__(256) k_pack() {
    int b = blockIdx.x >> 3;
    int w = blockIdx.x & 7;
    int j = threadIdx.x;

    const unsigned char* mk = ((const unsigned char*)g_masks4) + (size_t)b * HW + j;
    unsigned wd[6] = {0, 0, 0, 0, 0, 0};
    #pragma unroll 8
    for (int i2 = 0; i2 < 32; i2++) {
        unsigned m = mk[(w * 32 + i2) * WW];
        #pragma unroll
        for (int bit = 0; bit < 6; bit++)
            wd[bit] |= ((m >> bit) & 1u) << i2;
    }
    #pragma unroll
    for (int cc = 0; cc < 3; cc++) {
        int s = b * 3 + cc;
        g_bits[(0 * NSLICE + s) * 8 * WW + w * WW + j] = wd[cc];       // p-plane
        g_bits[(1 * NSLICE + s) * 8 * WW + w * WW + j] = wd[3 + cc];   // t-plane
    }

    // per-slice popcounts (for valid = any() && !all())
    __shared__ int scnt[6];
    if (threadIdx.x < 6) scnt[threadIdx.x] = 0;
    __syncthreads();
    #pragma unroll
    for (int bit = 0; bit < 6; bit++) {
        int tot = __reduce_add_sync(0xffffffffu, __popc(wd[bit]));
        if ((threadIdx.x & 31) == 0) atomicAdd(&scnt[bit], tot);
    }
    __syncthreads();
    if (threadIdx.x < 3)      atomicAdd(&g_cnt[b * 3 + threadIdx.x], scnt[threadIdx.x]);
    else if (threadIdx.x < 6) atomicAdd(&g_cnt[NSLICE + b * 3 + threadIdx.x - 3], scnt[threadIdx.x]);
}

// vertical distances (to nearest clear bit AND nearest set bit) in one column,
// from packed words. plane layout: [w][WW]. Exact, capped at 512.
__device__ __forceinline__ void vpair(const unsigned* __restrict__ plane, int j, int r,
                                      int& d_mask, int& d_comp, unsigned& cw_out) {
    int w0 = r >> 5, off = r & 31;
    unsigned cw = plane[w0 * WW + j];
    cw_out = cw;
    unsigned maskHi = 0xFFFFFFFFu << off;
    unsigned maskLo = 0xFFFFFFFFu >> (31 - off);

    int dn0 = CAP, dn1 = CAP;                 // downward: to clear, to set
    unsigned x0 = (~cw) & maskHi, x1 = cw & maskHi;
    if (x0) dn0 = (__ffs(x0) - 1) - off;
    if (x1) dn1 = (__ffs(x1) - 1) - off;
    for (int w = w0 + 1; w < 8 && (dn0 == CAP || dn1 == CAP); w++) {
        unsigned ww = plane[w * WW + j];
        if (dn0 == CAP && ~ww) dn0 = w * 32 + (__ffs(~ww) - 1) - r;
        if (dn1 == CAP &&  ww) dn1 = w * 32 + (__ffs(ww) - 1) - r;
    }
    int up0 = CAP, up1 = CAP;                 // upward
    unsigned y0 = (~cw) & maskLo, y1 = cw & maskLo;
    if (y0) up0 = off - (31 - __clz(y0));
    if (y1) up1 = off - (31 - __clz(y1));
    for (int w = w0 - 1; w >= 0 && (up0 == CAP || up1 == CAP); w--) {
        unsigned ww = plane[w * WW + j];
        if (up0 == CAP && ~ww) up0 = r - (w * 32 + 31 - __clz(~ww));
        if (up1 == CAP &&  ww) up1 = r - (w * 32 + 31 - __clz(ww));
    }
    d_mask = min(dn0, up0);
    d_comp = min(dn1, up1);
}

// exact outward search: min_k G[k] + (j-k)^2, early exit when d*d >= best
__device__ __forceinline__ int edt_search(const int* __restrict__ G, int j) {
    int best = G[j];
    #pragma unroll 4
    for (int d = 1; d < WW; d++) {
        int dd = d * d;
        if (dd >= best) break;
        int jm = j - d, jp = j + d;
        if (jm >= 0) best = min(best, G[jm] + dd);
        if (jp < WW) best = min(best, G[jp] + dd);
    }
    return best;
}

// -------- kernel 3: fused vertical EDT + horizontal EDT + loss reduction --------
__global__ void __launch_bounds__(256) k_main() {
    int s = blockIdx.x >> 8;       // slice 0..23
    int r = blockIdx.x & 255;      // row
    int j = threadIdx.x;           // column

    const unsigned* Pp = g_bits + (size_t)(0 * NSLICE + s) * 8 * WW;
    const unsigned* Pt = g_bits + (size_t)(1 * NSLICE + s) * 8 * WW;

    __shared__ int G[4][WW];
    unsigned cwp, cwt;
    int dm, dc;
    vpair(Pp, j, r, dm, dc, cwp);  G[0][j] = dm * dm;  G[1][j] = dc * dc;
    vpair(Pt, j, r, dm, dc, cwt);  G[2][j] = dm * dm;  G[3][j] = dc * dc;
    __syncthreads();

    int off = r & 31;
    int p_true = (cwp >> off) & 1;
    int t_true = (cwt >> off) & 1;

    // field = edt(m) + edt(~m): exactly one term nonzero, chosen by own mask bit
    int dp = edt_search(p_true ? G[0] : G[1], j);
    int dt = edt_search(t_true ? G[2] : G[3], j);

    int cp = g_cnt[s], ct = g_cnt[NSLICE + s];
    float vp = (cp > 0 && cp < HW) ? 1.0f : 0.0f;
    float vt = (ct > 0 && ct < HW) ? 1.0f : 0.0f;

    float p  = ((const float*)g_p4)[(size_t)s * HW + r * WW + j];
    float tg = (float)t_true;
    float err = (p - tg) * (p - tg);
    float val = err * ((float)dp * vp + (float)dt * vt);

    // block reduction -> double atomic
    #pragma unroll
    for (int o = 16; o; o >>= 1) val += __shfl_down_sync(0xffffffffu, val, o);
    __shared__ float wsum[8];
    if ((threadIdx.x & 31) == 0) wsum[threadIdx.x >> 5] = val;
    __syncthreads();
    if (threadIdx.x == 0) {
        float ssum = 0.0f;
        #pragma unroll
        for (int w = 0; w < 8; w++) ssum += wsum[w];
        atomicAdd(&g_acc, (double)ssum);
    }
}

// -------- kernel 4: finalize --------
__global__ void k_final(float* out) {
    double mean = g_acc / (double)(NSLICE * HW);
    out[0] = (float)log(mean + 1.0);
}

extern "C" void kernel_launch(void* const* d_in, const int* in_sizes, int n_in,
                              void* d_out, int out_size) {
    const float4* S = (const float4*)d_in[0];   // preds_S (8,4,256,256)
    const float4* T = (const float4*)d_in[1];   // preds_T (8,4,256,256)
    (void)in_sizes; (void)n_in; (void)out_size; // target (d_in[2]) unused by reference

    k_init<<<1, 64>>>();
    k_prep<<<NPIX / 4 / 256, 256>>>(S, T);
    k_pack<<<64, 256>>>();
    k_main<<<NSLICE * HH, 256>>>();
    k_final<<<1, 1>>>((float*)d_out);
}